// round 3
// baseline (speedup 1.0000x reference)
#include <cuda_runtime.h>

#define NN 50000
#define NE 600000
#define HID 128
#define TILE_N 64
#define KCH 32          // K-chunk for the GEMM

// Scratch (static device globals — no runtime allocation).
__device__ __align__(256) float g_q[(size_t)NN * HID];
__device__ __align__(256) float g_k[(size_t)NN * HID];
__device__ __align__(256) float g_v[(size_t)NN * HID];
__device__ __align__(256) float g_WT[3 * HID * HID];  // g_WT[m][d][o] = W_m[o][d]
__device__ __align__(256) int   g_src[NE];
__device__ __align__(256) int   g_dst[NE];
__device__ int g_is_i32;   // 1 if edge_index buffer is int32, 0 if int64

// ---------------------------------------------------------------------------
// Kernel A: dtype detection. The harness may deliver edge_index as int32
// (its documented type set) or raw int64. If int64 with indices < 2^31,
// every odd 32-bit word is 0. Scan all odd words; any nonzero => int32.
// ---------------------------------------------------------------------------
__global__ void detect_idx(const unsigned int* __restrict__ ei_words) {
    if (blockIdx.x == 0 && threadIdx.x == 0) g_is_i32 = 0;  // reset every call
    __threadfence();
    int t = blockIdx.x * blockDim.x + threadIdx.x;
    unsigned int acc = 0;
    // 2*NE odd words if int64 (4*NE words total); as int32 buffer it has
    // 2*NE words total -> only scan the first 2*NE words' odd positions,
    // which are valid in both interpretations.
    for (int i = t; i < NE; i += blockDim.x * gridDim.x)
        acc |= ei_words[2 * i + 1];
    if (acc) atomicOr(&g_is_i32, 1);
}

// ---------------------------------------------------------------------------
// Kernel B: decode edge_index into g_src / g_dst (int32).
// int32 layout: [src[0..E), dst[0..E)]   (words 0..2E)
// int64 layout: same logical rows, 2 words per element.
// ---------------------------------------------------------------------------
__global__ void convert_idx(const unsigned int* __restrict__ ei_words) {
    int t = blockIdx.x * blockDim.x + threadIdx.x;
    int i32 = g_is_i32;
    for (int e = t; e < NE; e += blockDim.x * gridDim.x) {
        int s, d;
        if (i32) {
            s = (int)ei_words[e];
            d = (int)ei_words[NE + e];
        } else {
            s = (int)ei_words[2 * (size_t)e];
            d = (int)ei_words[2 * ((size_t)NE + e)];
        }
        g_src[e] = s;
        g_dst[e] = d;
    }
}

// ---------------------------------------------------------------------------
// Kernel 0: transpose the three 128x128 weight matrices once (tiny).
// ---------------------------------------------------------------------------
__global__ void transpose_w(const float* __restrict__ Wq,
                            const float* __restrict__ Wk,
                            const float* __restrict__ Wv) {
    int t = blockIdx.x * blockDim.x + threadIdx.x;
    int total = 3 * HID * HID;
    for (int idx = t; idx < total; idx += blockDim.x * gridDim.x) {
        int m = idx / (HID * HID);
        int r = idx - m * (HID * HID);
        int o = r >> 7;
        int d = r & 127;
        const float* W = (m == 0) ? Wq : (m == 1) ? Wk : Wv;
        g_WT[m * HID * HID + d * HID + o] = W[o * HID + d];
    }
}

// ---------------------------------------------------------------------------
// Kernel 1: QKV projection GEMM. out[n][o] = sum_d x[n][d] * W[o][d]
// 256 threads, tile = 64 nodes x 128 outputs, K in chunks of 32 via static
// smem (24KB). Warp w owns nodes 8w..8w+7, lane l owns outputs 4l..4l+3.
// ---------------------------------------------------------------------------
__global__ __launch_bounds__(256) void qkv_gemm(const float* __restrict__ x) {
    __shared__ float wt[KCH][HID];      // transposed W chunk [d][o]
    __shared__ float xs[TILE_N][KCH];   // x tile chunk [n][d]

    int m = blockIdx.y;
    const float* wtg = &g_WT[m * HID * HID];
    float* out = (m == 0) ? g_q : (m == 1) ? g_k : g_v;

    int node0 = blockIdx.x * TILE_N;
    int tid = threadIdx.x;
    int w = tid >> 5;
    int l = tid & 31;

    float4 c[8];
#pragma unroll
    for (int n = 0; n < 8; n++) c[n] = make_float4(0.f, 0.f, 0.f, 0.f);

    for (int k0 = 0; k0 < HID; k0 += KCH) {
        {
            float4* wt4 = (float4*)&wt[0][0];
            const float4* src = (const float4*)&wtg[(size_t)k0 * HID];
#pragma unroll
            for (int i = 0; i < 4; i++)
                wt4[tid + i * 256] = src[tid + i * 256];
        }
        {
            float4* xs4 = (float4*)&xs[0][0];
            const float4* xg4 = (const float4*)x;
#pragma unroll
            for (int i = 0; i < 2; i++) {
                int idx = tid + i * 256;
                int n = idx >> 3;            // 8 float4 per row
                int c4 = idx & 7;
                int gn = node0 + n;
                float4 val = make_float4(0.f, 0.f, 0.f, 0.f);
                if (gn < NN) val = xg4[(size_t)gn * 32 + (k0 >> 2) + c4];
                xs4[idx] = val;
            }
        }
        __syncthreads();

#pragma unroll
        for (int d4 = 0; d4 < KCH / 4; d4++) {
            int d = d4 * 4;
            float4 wv0 = *(float4*)&wt[d + 0][4 * l];
            float4 wv1 = *(float4*)&wt[d + 1][4 * l];
            float4 wv2 = *(float4*)&wt[d + 2][4 * l];
            float4 wv3 = *(float4*)&wt[d + 3][4 * l];
#pragma unroll
            for (int n = 0; n < 8; n++) {
                float4 xv = *(float4*)&xs[8 * w + n][d];
                c[n].x = fmaf(xv.x, wv0.x, fmaf(xv.y, wv1.x, fmaf(xv.z, wv2.x, fmaf(xv.w, wv3.x, c[n].x))));
                c[n].y = fmaf(xv.x, wv0.y, fmaf(xv.y, wv1.y, fmaf(xv.z, wv2.y, fmaf(xv.w, wv3.y, c[n].y))));
                c[n].z = fmaf(xv.x, wv0.z, fmaf(xv.y, wv1.z, fmaf(xv.z, wv2.z, fmaf(xv.w, wv3.z, c[n].z))));
                c[n].w = fmaf(xv.x, wv0.w, fmaf(xv.y, wv1.w, fmaf(xv.z, wv2.w, fmaf(xv.w, wv3.w, c[n].w))));
            }
        }
        __syncthreads();
    }

#pragma unroll
    for (int n = 0; n < 8; n++) {
        int gn = node0 + 8 * w + n;
        if (gn < NN)
            *(float4*)&out[(size_t)gn * HID + 4 * l] = c[n];
    }
}

// ---------------------------------------------------------------------------
// Kernel 2: edge attention + scatter. One warp per edge. Lane l covers dims
// 4l..4l+3; 4 lanes = 1 head. Quad shfl-reduce -> per-head alpha; scalar
// RED.E.ADD.F32 scatter.
// ---------------------------------------------------------------------------
__global__ __launch_bounds__(256) void edge_kernel(
    const float* __restrict__ w_ij,
    const float* __restrict__ cutoff,
    float* __restrict__ out) {

    int e = (blockIdx.x * blockDim.x + threadIdx.x) >> 5;
    int l = threadIdx.x & 31;
    if (e >= NE) return;

    int src = g_src[e];
    int dst = g_dst[e];

    float4 q  = *(const float4*)&g_q[(size_t)dst * HID + 4 * l];
    float4 k  = *(const float4*)&g_k[(size_t)src * HID + 4 * l];
    float4 v  = *(const float4*)&g_v[(size_t)src * HID + 4 * l];
    float4 wv = *(const float4*)&w_ij[(size_t)e * HID + 4 * l];

    float p = q.x * wv.x * k.x + q.y * wv.y * k.y +
              q.z * wv.z * k.z + q.w * wv.w * k.w;
    p += __shfl_xor_sync(0xffffffffu, p, 1);
    p += __shfl_xor_sync(0xffffffffu, p, 2);

    float alpha = p * 0.25f * __ldg(&cutoff[e]);   // 1/sqrt(HEAD_DIM=16)

    float* op = &out[(size_t)dst * HID + 4 * l];
    atomicAdd(op + 0, alpha * v.x);
    atomicAdd(op + 1, alpha * v.y);
    atomicAdd(op + 2, alpha * v.z);
    atomicAdd(op + 3, alpha * v.w);
}

// ---------------------------------------------------------------------------
extern "C" void kernel_launch(void* const* d_in, const int* in_sizes, int n_in,
                              void* d_out, int out_size) {
    const float* x      = (const float*)d_in[0];
    const float* w_ij   = (const float*)d_in[1];
    const unsigned int* ei = (const unsigned int*)d_in[2];
    const float* cutoff = (const float*)d_in[3];
    const float* Wq     = (const float*)d_in[4];
    const float* Wk     = (const float*)d_in[5];
    const float* Wv     = (const float*)d_in[6];
    float* out = (float*)d_out;

    cudaMemsetAsync(out, 0, (size_t)out_size * sizeof(float));

    detect_idx<<<148, 256>>>(ei);
    convert_idx<<<148, 256>>>(ei);

    transpose_w<<<48, 256>>>(Wq, Wk, Wv);

    dim3 grid((NN + TILE_N - 1) / TILE_N, 3);
    qkv_gemm<<<grid, 256>>>(x);

    int nwarp_blocks = (NE * 32 + 255) / 256;   // 8 edges per 256-thread block
    edge_kernel<<<nwarp_blocks, 256>>>(w_ij, cutoff, out);
}

// round 4
// speedup vs baseline: 1.3218x; 1.3218x over previous
#include <cuda_runtime.h>

#define NN 50000
#define NE 600000
#define HID 128
#define TILE_N 64
#define KCH 32          // K-chunk for the GEMM

// Scratch (static device globals — no runtime allocation).
__device__ __align__(256) float g_q[(size_t)NN * HID];
__device__ __align__(256) float g_k[(size_t)NN * HID];
__device__ __align__(256) float g_v[(size_t)NN * HID];
__device__ __align__(256) float g_WT[3 * HID * HID];  // g_WT[m][d][o] = W_m[o][d]
__device__ __align__(256) int   g_src[NE];
__device__ __align__(256) int   g_dst[NE];
__device__ int g_is_i32;   // 1 if edge_index buffer is int32, 0 if int64

// ---------------------------------------------------------------------------
// Vector atomic: one red.global.add.v4.f32 replaces 4 scalar REDs (4x less
// LSU/atomic issue cost). Requires 16B-aligned address (guaranteed: out base
// + multiple of 16B).
// ---------------------------------------------------------------------------
__device__ __forceinline__ void red_add_v4(float* addr, float4 v) {
    asm volatile("red.global.add.v4.f32 [%0], {%1, %2, %3, %4};"
                 :: "l"(addr), "f"(v.x), "f"(v.y), "f"(v.z), "f"(v.w)
                 : "memory");
}

// ---------------------------------------------------------------------------
// Kernel A: dtype detection (int32 vs int64 edge_index). If int64 with
// indices < 2^31, every odd 32-bit word is 0.
// ---------------------------------------------------------------------------
__global__ void detect_idx(const unsigned int* __restrict__ ei_words) {
    if (blockIdx.x == 0 && threadIdx.x == 0) g_is_i32 = 0;  // reset every call
    __threadfence();
    int t = blockIdx.x * blockDim.x + threadIdx.x;
    unsigned int acc = 0;
    for (int i = t; i < NE; i += blockDim.x * gridDim.x)
        acc |= ei_words[2 * i + 1];
    if (acc) atomicOr(&g_is_i32, 1);
}

// ---------------------------------------------------------------------------
// Kernel B: decode edge_index into g_src / g_dst (int32).
// ---------------------------------------------------------------------------
__global__ void convert_idx(const unsigned int* __restrict__ ei_words) {
    int t = blockIdx.x * blockDim.x + threadIdx.x;
    int i32 = g_is_i32;
    for (int e = t; e < NE; e += blockDim.x * gridDim.x) {
        int s, d;
        if (i32) {
            s = (int)ei_words[e];
            d = (int)ei_words[NE + e];
        } else {
            s = (int)ei_words[2 * (size_t)e];
            d = (int)ei_words[2 * ((size_t)NE + e)];
        }
        g_src[e] = s;
        g_dst[e] = d;
    }
}

// ---------------------------------------------------------------------------
// Kernel 0: transpose the three 128x128 weight matrices once (tiny).
// ---------------------------------------------------------------------------
__global__ void transpose_w(const float* __restrict__ Wq,
                            const float* __restrict__ Wk,
                            const float* __restrict__ Wv) {
    int t = blockIdx.x * blockDim.x + threadIdx.x;
    int total = 3 * HID * HID;
    for (int idx = t; idx < total; idx += blockDim.x * gridDim.x) {
        int m = idx / (HID * HID);
        int r = idx - m * (HID * HID);
        int o = r >> 7;
        int d = r & 127;
        const float* W = (m == 0) ? Wq : (m == 1) ? Wk : Wv;
        g_WT[m * HID * HID + d * HID + o] = W[o * HID + d];
    }
}

// ---------------------------------------------------------------------------
// Kernel 1: QKV GEMM with register-staged prefetch of the next K-chunk so
// global-load latency hides under the FMA block. Tile = 64 nodes x 128 outs,
// K chunks of 32. Warp w owns nodes 8w..8w+7, lane l owns outputs 4l..4l+3.
// ---------------------------------------------------------------------------
__global__ __launch_bounds__(256) void qkv_gemm(const float* __restrict__ x) {
    __shared__ float wt[KCH][HID];      // transposed W chunk [d][o]
    __shared__ float xs[TILE_N][KCH];   // x tile chunk [n][d]

    int m = blockIdx.y;
    const float* wtg = &g_WT[m * HID * HID];
    float* out = (m == 0) ? g_q : (m == 1) ? g_k : g_v;

    int node0 = blockIdx.x * TILE_N;
    int tid = threadIdx.x;
    int w = tid >> 5;
    int l = tid & 31;

    const float4* xg4 = (const float4*)x;

    // Per-thread staging registers for one K-chunk.
    float4 wreg[4];     // 4 float4 of wt chunk
    float4 xreg[2];     // 2 float4 of xs chunk

    // x-tile addressing for this thread (fixed across chunks)
    int xn0 = (tid + 0 * 256) >> 3, xc0 = (tid + 0 * 256) & 7;
    int xn1 = (tid + 1 * 256) >> 3, xc1 = (tid + 1 * 256) & 7;
    int gn0 = node0 + xn0, gn1 = node0 + xn1;

    auto load_chunk = [&](int k0) {
        const float4* srcw = (const float4*)&wtg[(size_t)k0 * HID];
#pragma unroll
        for (int i = 0; i < 4; i++) wreg[i] = srcw[tid + i * 256];
        xreg[0] = (gn0 < NN) ? xg4[(size_t)gn0 * 32 + (k0 >> 2) + xc0]
                             : make_float4(0.f, 0.f, 0.f, 0.f);
        xreg[1] = (gn1 < NN) ? xg4[(size_t)gn1 * 32 + (k0 >> 2) + xc1]
                             : make_float4(0.f, 0.f, 0.f, 0.f);
    };
    auto store_chunk = [&]() {
        float4* wt4 = (float4*)&wt[0][0];
        float4* xs4 = (float4*)&xs[0][0];
#pragma unroll
        for (int i = 0; i < 4; i++) wt4[tid + i * 256] = wreg[i];
        xs4[tid] = xreg[0];
        xs4[tid + 256] = xreg[1];
    };

    float4 c[8];
#pragma unroll
    for (int n = 0; n < 8; n++) c[n] = make_float4(0.f, 0.f, 0.f, 0.f);

    load_chunk(0);
    store_chunk();
    __syncthreads();

#pragma unroll
    for (int kk = 0; kk < HID / KCH; kk++) {
        if (kk + 1 < HID / KCH)
            load_chunk((kk + 1) * KCH);   // LDG issued; hides under FMAs below

#pragma unroll
        for (int d4 = 0; d4 < KCH / 4; d4++) {
            int d = d4 * 4;
            float4 wv0 = *(float4*)&wt[d + 0][4 * l];
            float4 wv1 = *(float4*)&wt[d + 1][4 * l];
            float4 wv2 = *(float4*)&wt[d + 2][4 * l];
            float4 wv3 = *(float4*)&wt[d + 3][4 * l];
#pragma unroll
            for (int n = 0; n < 8; n++) {
                float4 xv = *(float4*)&xs[8 * w + n][d];
                c[n].x = fmaf(xv.x, wv0.x, fmaf(xv.y, wv1.x, fmaf(xv.z, wv2.x, fmaf(xv.w, wv3.x, c[n].x))));
                c[n].y = fmaf(xv.x, wv0.y, fmaf(xv.y, wv1.y, fmaf(xv.z, wv2.y, fmaf(xv.w, wv3.y, c[n].y))));
                c[n].z = fmaf(xv.x, wv0.z, fmaf(xv.y, wv1.z, fmaf(xv.z, wv2.z, fmaf(xv.w, wv3.z, c[n].z))));
                c[n].w = fmaf(xv.x, wv0.w, fmaf(xv.y, wv1.w, fmaf(xv.z, wv2.w, fmaf(xv.w, wv3.w, c[n].w))));
            }
        }
        __syncthreads();
        if (kk + 1 < HID / KCH) {
            store_chunk();
            __syncthreads();
        }
    }

#pragma unroll
    for (int n = 0; n < 8; n++) {
        int gn = node0 + 8 * w + n;
        if (gn < NN)
            *(float4*)&out[(size_t)gn * HID + 4 * l] = c[n];
    }
}

// ---------------------------------------------------------------------------
// Kernel 2: edge attention + scatter. One warp per edge; lane l covers dims
// 4l..4l+3 (4 lanes = 1 head). Quad shfl-reduce -> per-head alpha; single
// red.global.add.v4.f32 per lane for the scatter.
// ---------------------------------------------------------------------------
__global__ __launch_bounds__(256) void edge_kernel(
    const float* __restrict__ w_ij,
    const float* __restrict__ cutoff,
    float* __restrict__ out) {

    int e = (blockIdx.x * blockDim.x + threadIdx.x) >> 5;
    int l = threadIdx.x & 31;
    if (e >= NE) return;

    int src = g_src[e];
    int dst = g_dst[e];

    float4 q  = *(const float4*)&g_q[(size_t)dst * HID + 4 * l];
    float4 k  = *(const float4*)&g_k[(size_t)src * HID + 4 * l];
    float4 v  = *(const float4*)&g_v[(size_t)src * HID + 4 * l];
    float4 wv = *(const float4*)&w_ij[(size_t)e * HID + 4 * l];

    float p = q.x * wv.x * k.x + q.y * wv.y * k.y +
              q.z * wv.z * k.z + q.w * wv.w * k.w;
    p += __shfl_xor_sync(0xffffffffu, p, 1);
    p += __shfl_xor_sync(0xffffffffu, p, 2);

    float alpha = p * 0.25f * __ldg(&cutoff[e]);   // 1/sqrt(HEAD_DIM=16)

    float4 msg = make_float4(alpha * v.x, alpha * v.y, alpha * v.z, alpha * v.w);
    red_add_v4(&out[(size_t)dst * HID + 4 * l], msg);
}

// ---------------------------------------------------------------------------
extern "C" void kernel_launch(void* const* d_in, const int* in_sizes, int n_in,
                              void* d_out, int out_size) {
    const float* x      = (const float*)d_in[0];
    const float* w_ij   = (const float*)d_in[1];
    const unsigned int* ei = (const unsigned int*)d_in[2];
    const float* cutoff = (const float*)d_in[3];
    const float* Wq     = (const float*)d_in[4];
    const float* Wk     = (const float*)d_in[5];
    const float* Wv     = (const float*)d_in[6];
    float* out = (float*)d_out;

    cudaMemsetAsync(out, 0, (size_t)out_size * sizeof(float));

    detect_idx<<<148, 256>>>(ei);
    convert_idx<<<148, 256>>>(ei);

    transpose_w<<<48, 256>>>(Wq, Wk, Wv);

    dim3 grid((NN + TILE_N - 1) / TILE_N, 3);
    qkv_gemm<<<grid, 256>>>(x);

    int nwarp_blocks = (NE * 32 + 255) / 256;   // 8 edges per 256-thread block
    edge_kernel<<<nwarp_blocks, 256>>>(w_ij, cutoff, out);
}